// round 2
// baseline (speedup 1.0000x reference)
#include <cuda_runtime.h>

#define BSZ 4
#define NF  512
#define C8  64
#define HW  4096
#define QKV_ROWS 640   // 64 (q) + 64 (k) + 512 (v)

// Scratch: device globals (no allocation allowed in kernel_launch)
__device__ float g_qkv[(size_t)BSZ * QKV_ROWS * HW];          // ~41.9 MB
__device__ float g_attn[(size_t)BSZ * HW * HW];               // ~268 MB

__device__ __forceinline__ const float* w_row_ptr(int o, const float* Wq,
                                                  const float* Wk, const float* Wv) {
    if (o < C8)      return Wq + (size_t)o * NF;
    if (o < 2 * C8)  return Wk + (size_t)(o - C8) * NF;
    return Wv + (size_t)(o - 2 * C8) * NF;
}

__device__ __forceinline__ float bias_val(int o, const float* bq,
                                          const float* bk, const float* bv) {
    if (o < C8)      return bq[o];
    if (o < 2 * C8)  return bk[o - C8];
    return bv[o - 2 * C8];
}

// ---------------------------------------------------------------------------
// Kernel 1: QKV projection.  C[o,n] = sum_c W[o,c] * x[b,c,n] + bias[o]
// Tiling: 128x128x8, 256 threads, 8x8 micro-tile per thread.
// ---------------------------------------------------------------------------
__global__ __launch_bounds__(256) void qkv_kernel(
    const float* __restrict__ x,
    const float* __restrict__ Wq, const float* __restrict__ bq,
    const float* __restrict__ Wk, const float* __restrict__ bk,
    const float* __restrict__ Wv, const float* __restrict__ bv)
{
    const int b  = blockIdx.z;
    const int m0 = blockIdx.y * 128;
    const int n0 = blockIdx.x * 128;
    const float* xb  = x + (size_t)b * NF * HW;
    float* outp = g_qkv + (size_t)b * QKV_ROWS * HW;

    __shared__ float As[8][128];
    __shared__ float Bs[8][128];

    const int tid   = threadIdx.x;
    const int a_row = tid >> 1;          // 0..127  (m')
    const int a_c4  = (tid & 1) * 4;     // 0 or 4  (k offset)
    const int b_row = tid >> 5;          // 0..7    (k')
    const int b_c4  = (tid & 31) * 4;    // n offset
    const int tx = tid & 15, ty = tid >> 4;

    const float* wrow = w_row_ptr(m0 + a_row, Wq, Wk, Wv);

    float acc[8][8] = {};

    for (int k0 = 0; k0 < NF; k0 += 8) {
        float4 av = *(const float4*)(wrow + k0 + a_c4);
        As[a_c4 + 0][a_row] = av.x;
        As[a_c4 + 1][a_row] = av.y;
        As[a_c4 + 2][a_row] = av.z;
        As[a_c4 + 3][a_row] = av.w;
        *(float4*)&Bs[b_row][b_c4] =
            *(const float4*)(xb + (size_t)(k0 + b_row) * HW + n0 + b_c4);
        __syncthreads();
        #pragma unroll
        for (int k = 0; k < 8; ++k) {
            float ra[8], rb[8];
            *(float4*)&ra[0] = *(const float4*)&As[k][ty * 8];
            *(float4*)&ra[4] = *(const float4*)&As[k][ty * 8 + 4];
            *(float4*)&rb[0] = *(const float4*)&Bs[k][tx * 8];
            *(float4*)&rb[4] = *(const float4*)&Bs[k][tx * 8 + 4];
            #pragma unroll
            for (int i = 0; i < 8; ++i)
                #pragma unroll
                for (int j = 0; j < 8; ++j)
                    acc[i][j] += ra[i] * rb[j];
        }
        __syncthreads();
    }

    #pragma unroll
    for (int i = 0; i < 8; ++i) {
        const int m = m0 + ty * 8 + i;
        const float bias = bias_val(m, bq, bk, bv);
        float* crow = outp + (size_t)m * HW + n0 + tx * 8;
        #pragma unroll
        for (int j = 0; j < 8; j += 4) {
            float4 v4;
            v4.x = acc[i][j + 0] + bias;
            v4.y = acc[i][j + 1] + bias;
            v4.z = acc[i][j + 2] + bias;
            v4.w = acc[i][j + 3] + bias;
            *(float4*)(crow + j) = v4;
        }
    }
}

// ---------------------------------------------------------------------------
// Kernel 2: scores[i,j] = sum_c k[c,i] * q[c,j]   (TN GEMM, K=64)
// ---------------------------------------------------------------------------
__global__ __launch_bounds__(256) void scores_kernel()
{
    const int b  = blockIdx.z;
    const int m0 = blockIdx.y * 128;   // i
    const int n0 = blockIdx.x * 128;   // j
    const float* qp = g_qkv + (size_t)b * QKV_ROWS * HW;
    const float* kp = qp + (size_t)C8 * HW;
    float* cp = g_attn + (size_t)b * HW * HW;

    __shared__ float As[8][128];
    __shared__ float Bs[8][128];

    const int tid = threadIdx.x;
    const int r   = tid >> 5;          // 0..7
    const int c4  = (tid & 31) * 4;
    const int tx = tid & 15, ty = tid >> 4;

    float acc[8][8] = {};

    for (int k0 = 0; k0 < C8; k0 += 8) {
        *(float4*)&As[r][c4] = *(const float4*)(kp + (size_t)(k0 + r) * HW + m0 + c4);
        *(float4*)&Bs[r][c4] = *(const float4*)(qp + (size_t)(k0 + r) * HW + n0 + c4);
        __syncthreads();
        #pragma unroll
        for (int k = 0; k < 8; ++k) {
            float ra[8], rb[8];
            *(float4*)&ra[0] = *(const float4*)&As[k][ty * 8];
            *(float4*)&ra[4] = *(const float4*)&As[k][ty * 8 + 4];
            *(float4*)&rb[0] = *(const float4*)&Bs[k][tx * 8];
            *(float4*)&rb[4] = *(const float4*)&Bs[k][tx * 8 + 4];
            #pragma unroll
            for (int i = 0; i < 8; ++i)
                #pragma unroll
                for (int j = 0; j < 8; ++j)
                    acc[i][j] += ra[i] * rb[j];
        }
        __syncthreads();
    }

    #pragma unroll
    for (int i = 0; i < 8; ++i) {
        float* crow = cp + (size_t)(m0 + ty * 8 + i) * HW + n0 + tx * 8;
        #pragma unroll
        for (int j = 0; j < 8; j += 4) {
            float4 v4;
            v4.x = acc[i][j + 0];
            v4.y = acc[i][j + 1];
            v4.z = acc[i][j + 2];
            v4.w = acc[i][j + 3];
            *(float4*)(crow + j) = v4;
        }
    }
}

// ---------------------------------------------------------------------------
// Kernel 3: row softmax over last axis (4096). One block per row, row kept
// in registers -> single global read + single write.
// ---------------------------------------------------------------------------
__device__ __forceinline__ float warp_max(float v) {
    #pragma unroll
    for (int o = 16; o > 0; o >>= 1) v = fmaxf(v, __shfl_xor_sync(0xffffffffu, v, o));
    return v;
}
__device__ __forceinline__ float warp_sum(float v) {
    #pragma unroll
    for (int o = 16; o > 0; o >>= 1) v += __shfl_xor_sync(0xffffffffu, v, o);
    return v;
}

__global__ __launch_bounds__(256) void softmax_kernel()
{
    float* p = g_attn + (size_t)blockIdx.x * HW;
    const int tid = threadIdx.x;

    float4 v[4];
    #pragma unroll
    for (int i = 0; i < 4; ++i)
        v[i] = ((const float4*)p)[tid + 256 * i];

    float m = -3.4e38f;
    #pragma unroll
    for (int i = 0; i < 4; ++i) {
        m = fmaxf(m, fmaxf(fmaxf(v[i].x, v[i].y), fmaxf(v[i].z, v[i].w)));
    }

    __shared__ float red[8];
    float wm = warp_max(m);
    if ((tid & 31) == 0) red[tid >> 5] = wm;
    __syncthreads();
    float bm = red[0];
    #pragma unroll
    for (int i = 1; i < 8; ++i) bm = fmaxf(bm, red[i]);

    float s = 0.0f;
    #pragma unroll
    for (int i = 0; i < 4; ++i) {
        v[i].x = __expf(v[i].x - bm);
        v[i].y = __expf(v[i].y - bm);
        v[i].z = __expf(v[i].z - bm);
        v[i].w = __expf(v[i].w - bm);
        s += v[i].x + v[i].y + v[i].z + v[i].w;
    }
    __syncthreads();          // red[] reuse
    float ws = warp_sum(s);
    if ((tid & 31) == 0) red[tid >> 5] = ws;
    __syncthreads();
    float total = 0.0f;
    #pragma unroll
    for (int i = 0; i < 8; ++i) total += red[i];
    const float inv = 1.0f / total;

    #pragma unroll
    for (int i = 0; i < 4; ++i) {
        v[i].x *= inv; v[i].y *= inv; v[i].z *= inv; v[i].w *= inv;
        ((float4*)p)[tid + 256 * i] = v[i];
    }
}

// ---------------------------------------------------------------------------
// Kernel 4: out[c,i] = x[c,i] + alpha * sum_j v[c,j] * attn[i,j]
// NT GEMM: M=512 (c), N=4096 (i), K=4096 (j). Residual fused in epilogue.
// ---------------------------------------------------------------------------
__global__ __launch_bounds__(256) void out_kernel(
    const float* __restrict__ x,
    const float* __restrict__ alphap,
    float* __restrict__ out)
{
    const int b  = blockIdx.z;
    const int m0 = blockIdx.y * 128;   // c
    const int n0 = blockIdx.x * 128;   // i
    const float* vp = g_qkv + (size_t)b * QKV_ROWS * HW + (size_t)(2 * C8) * HW;
    const float* ap = g_attn + (size_t)b * HW * HW;
    const float* xb = x + (size_t)b * NF * HW;
    float* ob = out + (size_t)b * NF * HW;

    __shared__ float As[8][128];
    __shared__ float Bs[8][128];

    const int tid = threadIdx.x;
    const int row = tid >> 1;          // 0..127
    const int c4  = (tid & 1) * 4;     // 0 or 4 (k offset)
    const int tx = tid & 15, ty = tid >> 4;

    float acc[8][8] = {};

    for (int k0 = 0; k0 < HW; k0 += 8) {
        float4 av = *(const float4*)(vp + (size_t)(m0 + row) * HW + k0 + c4);
        As[c4 + 0][row] = av.x;
        As[c4 + 1][row] = av.y;
        As[c4 + 2][row] = av.z;
        As[c4 + 3][row] = av.w;
        float4 bv4 = *(const float4*)(ap + (size_t)(n0 + row) * HW + k0 + c4);
        Bs[c4 + 0][row] = bv4.x;
        Bs[c4 + 1][row] = bv4.y;
        Bs[c4 + 2][row] = bv4.z;
        Bs[c4 + 3][row] = bv4.w;
        __syncthreads();
        #pragma unroll
        for (int k = 0; k < 8; ++k) {
            float ra[8], rb[8];
            *(float4*)&ra[0] = *(const float4*)&As[k][ty * 8];
            *(float4*)&ra[4] = *(const float4*)&As[k][ty * 8 + 4];
            *(float4*)&rb[0] = *(const float4*)&Bs[k][tx * 8];
            *(float4*)&rb[4] = *(const float4*)&Bs[k][tx * 8 + 4];
            #pragma unroll
            for (int i = 0; i < 8; ++i)
                #pragma unroll
                for (int j = 0; j < 8; ++j)
                    acc[i][j] += ra[i] * rb[j];
        }
        __syncthreads();
    }

    const float alpha = alphap[0];
    #pragma unroll
    for (int i = 0; i < 8; ++i) {
        const size_t base = (size_t)(m0 + ty * 8 + i) * HW + n0 + tx * 8;
        #pragma unroll
        for (int j = 0; j < 8; j += 4) {
            float4 xv = *(const float4*)(xb + base + j);
            float4 v4;
            v4.x = xv.x + alpha * acc[i][j + 0];
            v4.y = xv.y + alpha * acc[i][j + 1];
            v4.z = xv.z + alpha * acc[i][j + 2];
            v4.w = xv.w + alpha * acc[i][j + 3];
            *(float4*)(ob + base + j) = v4;
        }
    }
}

// ---------------------------------------------------------------------------
extern "C" void kernel_launch(void* const* d_in, const int* in_sizes, int n_in,
                              void* d_out, int out_size)
{
    const float* x     = (const float*)d_in[0];
    const float* Wq    = (const float*)d_in[1];
    const float* bq    = (const float*)d_in[2];
    const float* Wk    = (const float*)d_in[3];
    const float* bk    = (const float*)d_in[4];
    const float* Wv    = (const float*)d_in[5];
    const float* bv    = (const float*)d_in[6];
    const float* alpha = (const float*)d_in[7];
    float* out = (float*)d_out;

    qkv_kernel<<<dim3(HW / 128, QKV_ROWS / 128, BSZ), 256>>>(x, Wq, bq, Wk, bk, Wv, bv);
    scores_kernel<<<dim3(HW / 128, HW / 128, BSZ), 256>>>();
    softmax_kernel<<<BSZ * HW, 256>>>();
    out_kernel<<<dim3(HW / 128, NF / 128, BSZ), 256>>>(x, alpha, out);
}

// round 8
// speedup vs baseline: 2.9063x; 2.9063x over previous
#include <cuda_runtime.h>

#define BSZ 4
#define NF  512
#define C8  64
#define HW  4096
#define QKV_ROWS 640   // 64 (q) + 64 (k) + 512 (v)

__device__ float g_qkv[(size_t)BSZ * QKV_ROWS * HW];          // ~41.9 MB
__device__ float g_attn[(size_t)BSZ * HW * HW];               // ~268 MB

// ---------------------------------------------------------------------------
// Helpers
// ---------------------------------------------------------------------------
__device__ __forceinline__ unsigned f2tf32(float f) {
    unsigned u;
    asm("cvt.rna.tf32.f32 %0, %1;" : "=r"(u) : "f"(f));
    return u;
}
__device__ __forceinline__ void split_tf32(float v, unsigned& hi, unsigned& lo) {
    hi = f2tf32(v);
    lo = f2tf32(v - __uint_as_float(hi));
}

__device__ __forceinline__ void mma16n8k8(float* c, const unsigned* a, const unsigned* b) {
    asm volatile(
        "mma.sync.aligned.m16n8k8.row.col.f32.tf32.tf32.f32 "
        "{%0,%1,%2,%3}, {%4,%5,%6,%7}, {%8,%9}, {%0,%1,%2,%3};\n"
        : "+f"(c[0]), "+f"(c[1]), "+f"(c[2]), "+f"(c[3])
        : "r"(a[0]), "r"(a[1]), "r"(a[2]), "r"(a[3]), "r"(b[0]), "r"(b[1]));
}

#define CP_ASYNC16(smem_u32, gptr) \
    asm volatile("cp.async.cg.shared.global [%0], [%1], 16;\n" :: "r"(smem_u32), "l"(gptr))
#define CP_COMMIT() asm volatile("cp.async.commit_group;\n" ::: "memory")
#define CP_WAIT0()  asm volatile("cp.async.wait_group 0;\n" ::: "memory")

// XOR swizzle for transposed [k][128] tiles: flips bits 3-4 of the column
#define SWZ(k, col) ((col) ^ (((k) & 3) << 3))

__device__ __forceinline__ const float* w_row_ptr(int o, const float* Wq,
                                                  const float* Wk, const float* Wv) {
    if (o < C8)      return Wq + (size_t)o * NF;
    if (o < 2 * C8)  return Wk + (size_t)(o - C8) * NF;
    return Wv + (size_t)(o - 2 * C8) * NF;
}
__device__ __forceinline__ float bias_val(int o, const float* bq,
                                          const float* bk, const float* bv) {
    if (o < C8)      return bq[o];
    if (o < 2 * C8)  return bk[o - C8];
    return bv[o - 2 * C8];
}

// ---------------------------------------------------------------------------
// Kernel 1: QKV projection. C[o,n] = sum_c W[o,c]*x[b,c,n] + bias[o]
// A = W row-major [m][k] (stride-20 pad, conflict-free)
// B = x  transposed [k][n], XOR-swizzled, 512 chunks/stage (coverage fixed)
// HP: 3xTF32 for the q/k rows (exp-amplified path). LP: 1xTF32 for v rows.
// ---------------------------------------------------------------------------
template<bool HP>
__global__ __launch_bounds__(256) void qkv_mma(
    const float* __restrict__ x,
    const float* __restrict__ Wq, const float* __restrict__ bq,
    const float* __restrict__ Wk, const float* __restrict__ bk,
    const float* __restrict__ Wv, const float* __restrict__ bv,
    int m_base)
{
    __shared__ float As[2][128][20];
    __shared__ float Bs[2][16][128];

    const int b     = blockIdx.z;
    const int m_blk = m_base + blockIdx.y * 128;
    const int n_blk = blockIdx.x * 128;
    const float* xb = x + (size_t)b * NF * HW;
    float* outp     = g_qkv + (size_t)b * QKV_ROWS * HW;

    const int tid  = threadIdx.x;
    const int warp = tid >> 5, lane = tid & 31;
    const int g    = lane >> 2, tig = lane & 3;
    const int wm   = (warp >> 2) * 64, wn = (warp & 3) * 32;

    const unsigned as0 = (unsigned)__cvta_generic_to_shared(&As[0][0][0]);
    const unsigned bs0 = (unsigned)__cvta_generic_to_shared(&Bs[0][0][0]);

    float acc[4][4][4] = {};
    const int T = NF / 16;   // 32

    // prefetch helper logic (inlined): A chunks c=tid, tid+256 ; B same
    {
        const int k0 = 0;
        int c = tid, row = c >> 2, off = (c & 3) * 4;
        CP_ASYNC16(as0 + row * 80 + off * 4, w_row_ptr(m_blk + row, Wq, Wk, Wv) + k0 + off);
        c = tid + 256; row = c >> 2; off = (c & 3) * 4;
        CP_ASYNC16(as0 + row * 80 + off * 4, w_row_ptr(m_blk + row, Wq, Wk, Wv) + k0 + off);
        c = tid;       { int r = c >> 5, o2 = (c & 31) * 4, sw = SWZ(r, o2);
            CP_ASYNC16(bs0 + r * 512 + sw * 4, xb + (size_t)(k0 + r) * HW + n_blk + o2); }
        c = tid + 256; { int r = c >> 5, o2 = (c & 31) * 4, sw = SWZ(r, o2);
            CP_ASYNC16(bs0 + r * 512 + sw * 4, xb + (size_t)(k0 + r) * HW + n_blk + o2); }
        CP_COMMIT();
    }

    for (int t = 0; t < T; ++t) {
        CP_WAIT0();
        __syncthreads();
        if (t + 1 < T) {
            const int s = (t + 1) & 1;
            const int k0 = (t + 1) * 16;
            int c = tid, row = c >> 2, off = (c & 3) * 4;
            CP_ASYNC16(as0 + s * 10240 + row * 80 + off * 4,
                       w_row_ptr(m_blk + row, Wq, Wk, Wv) + k0 + off);
            c = tid + 256; row = c >> 2; off = (c & 3) * 4;
            CP_ASYNC16(as0 + s * 10240 + row * 80 + off * 4,
                       w_row_ptr(m_blk + row, Wq, Wk, Wv) + k0 + off);
            c = tid;       { int r = c >> 5, o2 = (c & 31) * 4, sw = SWZ(r, o2);
                CP_ASYNC16(bs0 + s * 8192 + r * 512 + sw * 4,
                           xb + (size_t)(k0 + r) * HW + n_blk + o2); }
            c = tid + 256; { int r = c >> 5, o2 = (c & 31) * 4, sw = SWZ(r, o2);
                CP_ASYNC16(bs0 + s * 8192 + r * 512 + sw * 4,
                           xb + (size_t)(k0 + r) * HW + n_blk + o2); }
            CP_COMMIT();
        }
        const int s = t & 1;
        #pragma unroll
        for (int ks = 0; ks < 16; ks += 8) {
            unsigned af[4][4], bf[4][2];
            unsigned afl[4][4], bfl[4][2];
            #pragma unroll
            for (int mi = 0; mi < 4; ++mi) {
                const int row = wm + mi * 16 + g;
                float a0 = As[s][row][ks + tig];
                float a1 = As[s][row + 8][ks + tig];
                float a2 = As[s][row][ks + tig + 4];
                float a3 = As[s][row + 8][ks + tig + 4];
                if (HP) {
                    split_tf32(a0, af[mi][0], afl[mi][0]);
                    split_tf32(a1, af[mi][1], afl[mi][1]);
                    split_tf32(a2, af[mi][2], afl[mi][2]);
                    split_tf32(a3, af[mi][3], afl[mi][3]);
                } else {
                    af[mi][0] = f2tf32(a0); af[mi][1] = f2tf32(a1);
                    af[mi][2] = f2tf32(a2); af[mi][3] = f2tf32(a3);
                }
            }
            #pragma unroll
            for (int ni = 0; ni < 4; ++ni) {
                const int n = wn + ni * 8 + g;
                const int k0q = ks + tig, k1q = ks + tig + 4;
                float b0 = Bs[s][k0q][SWZ(k0q, n)];
                float b1 = Bs[s][k1q][SWZ(k1q, n)];
                if (HP) {
                    split_tf32(b0, bf[ni][0], bfl[ni][0]);
                    split_tf32(b1, bf[ni][1], bfl[ni][1]);
                } else {
                    bf[ni][0] = f2tf32(b0); bf[ni][1] = f2tf32(b1);
                }
            }
            #pragma unroll
            for (int mi = 0; mi < 4; ++mi)
                #pragma unroll
                for (int ni = 0; ni < 4; ++ni) {
                    mma16n8k8(acc[mi][ni], af[mi], bf[ni]);
                    if (HP) {
                        mma16n8k8(acc[mi][ni], afl[mi], bf[ni]);
                        mma16n8k8(acc[mi][ni], af[mi], bfl[ni]);
                    }
                }
        }
    }

    #pragma unroll
    for (int mi = 0; mi < 4; ++mi) {
        #pragma unroll
        for (int ni = 0; ni < 4; ++ni) {
            const int m = m_blk + wm + mi * 16 + g;
            const int n = n_blk + wn + ni * 8 + tig * 2;
            const float bias0 = bias_val(m, bq, bk, bv);
            const float bias1 = bias_val(m + 8, bq, bk, bv);
            float2 r0 = { acc[mi][ni][0] + bias0, acc[mi][ni][1] + bias0 };
            float2 r1 = { acc[mi][ni][2] + bias1, acc[mi][ni][3] + bias1 };
            *(float2*)(outp + (size_t)m * HW + n)       = r0;
            *(float2*)(outp + (size_t)(m + 8) * HW + n) = r1;
        }
    }
}

// ---------------------------------------------------------------------------
// Kernel 2: scores[i,j] = sum_c k[c,i]*q[c,j]  (3xTF32, K=64)
// Both tiles transposed [k][128], XOR-swizzled, full 512-chunk coverage.
// ---------------------------------------------------------------------------
__global__ __launch_bounds__(256) void scores_mma()
{
    __shared__ float Ks[2][16][128];
    __shared__ float Qs[2][16][128];

    const int b     = blockIdx.z;
    const int m_blk = blockIdx.y * 128;   // i
    const int n_blk = blockIdx.x * 128;   // j
    const float* qp = g_qkv + (size_t)b * QKV_ROWS * HW;
    const float* kp = qp + (size_t)C8 * HW;
    float* cp = g_attn + (size_t)b * HW * HW;

    const int tid  = threadIdx.x;
    const int warp = tid >> 5, lane = tid & 31;
    const int g    = lane >> 2, tig = lane & 3;
    const int wm   = (warp >> 2) * 64, wn = (warp & 3) * 32;

    const unsigned ks0 = (unsigned)__cvta_generic_to_shared(&Ks[0][0][0]);
    const unsigned qs0 = (unsigned)__cvta_generic_to_shared(&Qs[0][0][0]);

    float acc[4][4][4] = {};
    const int T = C8 / 16;   // 4

    {
        const int k0 = 0;
        #pragma unroll
        for (int h = 0; h < 2; ++h) {
            const int c = tid + h * 256;
            const int r = c >> 5, o2 = (c & 31) * 4, sw = SWZ(r, o2);
            CP_ASYNC16(ks0 + r * 512 + sw * 4, kp + (size_t)(k0 + r) * HW + m_blk + o2);
            CP_ASYNC16(qs0 + r * 512 + sw * 4, qp + (size_t)(k0 + r) * HW + n_blk + o2);
        }
        CP_COMMIT();
    }

    for (int t = 0; t < T; ++t) {
        CP_WAIT0();
        __syncthreads();
        if (t + 1 < T) {
            const int s = (t + 1) & 1;
            const int k0 = (t + 1) * 16;
            #pragma unroll
            for (int h = 0; h < 2; ++h) {
                const int c = tid + h * 256;
                const int r = c >> 5, o2 = (c & 31) * 4, sw = SWZ(r, o2);
                CP_ASYNC16(ks0 + s * 8192 + r * 512 + sw * 4,
                           kp + (size_t)(k0 + r) * HW + m_blk + o2);
                CP_ASYNC16(qs0 + s * 8192 + r * 512 + sw * 4,
                           qp + (size_t)(k0 + r) * HW + n_blk + o2);
            }
            CP_COMMIT();
        }
        const int s = t & 1;
        #pragma unroll
        for (int ks = 0; ks < 16; ks += 8) {
            const int ka = ks + tig, kb = ks + tig + 4;
            unsigned af[4][4], afl[4][4], bf[4][2], bfl[4][2];
            #pragma unroll
            for (int mi = 0; mi < 4; ++mi) {
                const int m = wm + mi * 16 + g;
                split_tf32(Ks[s][ka][SWZ(ka, m)],     af[mi][0], afl[mi][0]);
                split_tf32(Ks[s][ka][SWZ(ka, m + 8)], af[mi][1], afl[mi][1]);
                split_tf32(Ks[s][kb][SWZ(kb, m)],     af[mi][2], afl[mi][2]);
                split_tf32(Ks[s][kb][SWZ(kb, m + 8)], af[mi][3], afl[mi][3]);
            }
            #pragma unroll
            for (int ni = 0; ni < 4; ++ni) {
                const int n = wn + ni * 8 + g;
                split_tf32(Qs[s][ka][SWZ(ka, n)], bf[ni][0], bfl[ni][0]);
                split_tf32(Qs[s][kb][SWZ(kb, n)], bf[ni][1], bfl[ni][1]);
            }
            #pragma unroll
            for (int mi = 0; mi < 4; ++mi)
                #pragma unroll
                for (int ni = 0; ni < 4; ++ni) {
                    mma16n8k8(acc[mi][ni], af[mi], bf[ni]);
                    mma16n8k8(acc[mi][ni], afl[mi], bf[ni]);
                    mma16n8k8(acc[mi][ni], af[mi], bfl[ni]);
                }
        }
    }

    #pragma unroll
    for (int mi = 0; mi < 4; ++mi) {
        #pragma unroll
        for (int ni = 0; ni < 4; ++ni) {
            const int m = m_blk + wm + mi * 16 + g;
            const int n = n_blk + wn + ni * 8 + tig * 2;
            *(float2*)(cp + (size_t)m * HW + n)       = make_float2(acc[mi][ni][0], acc[mi][ni][1]);
            *(float2*)(cp + (size_t)(m + 8) * HW + n) = make_float2(acc[mi][ni][2], acc[mi][ni][3]);
        }
    }
}

// ---------------------------------------------------------------------------
// Kernel 3: row softmax over last axis (4096). One block per row.
// ---------------------------------------------------------------------------
__device__ __forceinline__ float warp_max(float v) {
    #pragma unroll
    for (int o = 16; o > 0; o >>= 1) v = fmaxf(v, __shfl_xor_sync(0xffffffffu, v, o));
    return v;
}
__device__ __forceinline__ float warp_sum(float v) {
    #pragma unroll
    for (int o = 16; o > 0; o >>= 1) v += __shfl_xor_sync(0xffffffffu, v, o);
    return v;
}

__global__ __launch_bounds__(256) void softmax_kernel()
{
    float* p = g_attn + (size_t)blockIdx.x * HW;
    const int tid = threadIdx.x;

    float4 v[4];
    #pragma unroll
    for (int i = 0; i < 4; ++i)
        v[i] = ((const float4*)p)[tid + 256 * i];

    float m = -3.4e38f;
    #pragma unroll
    for (int i = 0; i < 4; ++i)
        m = fmaxf(m, fmaxf(fmaxf(v[i].x, v[i].y), fmaxf(v[i].z, v[i].w)));

    __shared__ float red[8];
    float wm = warp_max(m);
    if ((tid & 31) == 0) red[tid >> 5] = wm;
    __syncthreads();
    float bm = red[0];
    #pragma unroll
    for (int i = 1; i < 8; ++i) bm = fmaxf(bm, red[i]);

    float s = 0.0f;
    #pragma unroll
    for (int i = 0; i < 4; ++i) {
        v[i].x = __expf(v[i].x - bm);
        v[i].y = __expf(v[i].y - bm);
        v[i].z = __expf(v[i].z - bm);
        v[i].w = __expf(v[i].w - bm);
        s += v[i].x + v[i].y + v[i].z + v[i].w;
    }
    __syncthreads();
    float ws = warp_sum(s);
    if ((tid & 31) == 0) red[tid >> 5] = ws;
    __syncthreads();
    float total = 0.0f;
    #pragma unroll
    for (int i = 0; i < 8; ++i) total += red[i];
    const float inv = 1.0f / total;

    #pragma unroll
    for (int i = 0; i < 4; ++i) {
        v[i].x *= inv; v[i].y *= inv; v[i].z *= inv; v[i].w *= inv;
        ((float4*)p)[tid + 256 * i] = v[i];
    }
}

// ---------------------------------------------------------------------------
// Kernel 4: out[c,i] = x[c,i] + alpha * sum_j v[c,j]*attn[i,j]  (1xTF32)
// A = v row-major [m][k], B = attn row-major [n][k]; stride-20 pads (clean).
// ---------------------------------------------------------------------------
__global__ __launch_bounds__(256, 2) void out_mma(
    const float* __restrict__ x,
    const float* __restrict__ alphap,
    float* __restrict__ out)
{
    __shared__ float As[2][128][20];
    __shared__ float Bs[2][128][20];

    const int b     = blockIdx.z;
    const int m_blk = blockIdx.y * 128;   // c
    const int n_blk = blockIdx.x * 128;   // i
    const float* vp = g_qkv + (size_t)b * QKV_ROWS * HW + (size_t)(2 * C8) * HW;
    const float* ap = g_attn + (size_t)b * HW * HW;
    const float* xb = x + (size_t)b * NF * HW;
    float* ob = out + (size_t)b * NF * HW;

    const int tid  = threadIdx.x;
    const int warp = tid >> 5, lane = tid & 31;
    const int g    = lane >> 2, tig = lane & 3;
    const int wm   = (warp >> 2) * 64, wn = (warp & 3) * 32;

    const unsigned as0 = (unsigned)__cvta_generic_to_shared(&As[0][0][0]);
    const unsigned bs0 = (unsigned)__cvta_generic_to_shared(&Bs[0][0][0]);

    float acc[4][4][4] = {};
    const int T = HW / 16;   // 256

    {
        const int k0 = 0;
        #pragma unroll
        for (int h = 0; h < 2; ++h) {
            const int c = tid + h * 256;
            const int row = c >> 2, off = (c & 3) * 4;
            CP_ASYNC16(as0 + row * 80 + off * 4, vp + (size_t)(m_blk + row) * HW + k0 + off);
            CP_ASYNC16(bs0 + row * 80 + off * 4, ap + (size_t)(n_blk + row) * HW + k0 + off);
        }
        CP_COMMIT();
    }

    for (int t = 0; t < T; ++t) {
        CP_WAIT0();
        __syncthreads();
        if (t + 1 < T) {
            const int s = (t + 1) & 1;
            const int k0 = (t + 1) * 16;
            #pragma unroll
            for (int h = 0; h < 2; ++h) {
                const int c = tid + h * 256;
                const int row = c >> 2, off = (c & 3) * 4;
                CP_ASYNC16(as0 + s * 10240 + row * 80 + off * 4,
                           vp + (size_t)(m_blk + row) * HW + k0 + off);
                CP_ASYNC16(bs0 + s * 10240 + row * 80 + off * 4,
                           ap + (size_t)(n_blk + row) * HW + k0 + off);
            }
            CP_COMMIT();
        }
        const int s = t & 1;
        #pragma unroll
        for (int ks = 0; ks < 16; ks += 8) {
            unsigned af[4][4], bf[4][2];
            #pragma unroll
            for (int mi = 0; mi < 4; ++mi) {
                const int row = wm + mi * 16 + g;
                af[mi][0] = f2tf32(As[s][row][ks + tig]);
                af[mi][1] = f2tf32(As[s][row + 8][ks + tig]);
                af[mi][2] = f2tf32(As[s][row][ks + tig + 4]);
                af[mi][3] = f2tf32(As[s][row + 8][ks + tig + 4]);
            }
            #pragma unroll
            for (int ni = 0; ni < 4; ++ni) {
                const int n = wn + ni * 8 + g;
                bf[ni][0] = f2tf32(Bs[s][n][ks + tig]);
                bf[ni][1] = f2tf32(Bs[s][n][ks + tig + 4]);
            }
            #pragma unroll
            for (int mi = 0; mi < 4; ++mi)
                #pragma unroll
                for (int ni = 0; ni < 4; ++ni)
                    mma16n8k8(acc[mi][ni], af[mi], bf[ni]);
        }
    }

    const float alpha = alphap[0];
    #pragma unroll
    for (int mi = 0; mi < 4; ++mi) {
        #pragma unroll
        for (int ni = 0; ni < 4; ++ni) {
            const int m = m_blk + wm + mi * 16 + g;
            const int n = n_blk + wn + ni * 8 + tig * 2;
            const size_t i0 = (size_t)m * HW + n;
            const size_t i1 = (size_t)(m + 8) * HW + n;
            float2 x0 = *(const float2*)(xb + i0);
            float2 x1 = *(const float2*)(xb + i1);
            float2 r0 = { x0.x + alpha * acc[mi][ni][0], x0.y + alpha * acc[mi][ni][1] };
            float2 r1 = { x1.x + alpha * acc[mi][ni][2], x1.y + alpha * acc[mi][ni][3] };
            *(float2*)(ob + i0) = r0;
            *(float2*)(ob + i1) = r1;
        }
    }
}

// ---------------------------------------------------------------------------
extern "C" void kernel_launch(void* const* d_in, const int* in_sizes, int n_in,
                              void* d_out, int out_size)
{
    const float* x     = (const float*)d_in[0];
    const float* Wq    = (const float*)d_in[1];
    const float* bq    = (const float*)d_in[2];
    const float* Wk    = (const float*)d_in[3];
    const float* bk    = (const float*)d_in[4];
    const float* Wv    = (const float*)d_in[5];
    const float* bv    = (const float*)d_in[6];
    const float* alpha = (const float*)d_in[7];
    float* out = (float*)d_out;

    // q/k rows (0..127): high precision (3xTF32)
    qkv_mma<true><<<dim3(HW / 128, 1, BSZ), 256>>>(x, Wq, bq, Wk, bk, Wv, bv, 0);
    // v rows (128..639): 1xTF32
    qkv_mma<false><<<dim3(HW / 128, 4, BSZ), 256>>>(x, Wq, bq, Wk, bk, Wv, bv, 128);
    scores_mma<<<dim3(HW / 128, HW / 128, BSZ), 256>>>();
    softmax_kernel<<<BSZ * HW, 256>>>();
    out_mma<<<dim3(HW / 128, NF / 128, BSZ), 256>>>(x, alpha, out);
}

// round 9
// speedup vs baseline: 3.9854x; 1.3713x over previous
#include <cuda_runtime.h>
#include <cuda_bf16.h>

#define BSZ 4
#define NF  512
#define C8  64
#define HW  4096

// Scratch (device globals; no allocation allowed in kernel_launch)
__device__ float         g_qk  [(size_t)BSZ * 2 * C8 * HW];   // q(64)+k(64) rows, fp32, 8.4MB
__device__ __nv_bfloat16 g_vbf [(size_t)BSZ * NF * HW];       // v in bf16, 16.8MB
__device__ float         g_attn[(size_t)BSZ * HW * HW];       // raw scores fp32, 268MB
__device__ __nv_bfloat16 g_attn_bf[(size_t)BSZ * HW * HW];    // softmaxed attn bf16, 134MB

// ---------------------------------------------------------------------------
// Helpers
// ---------------------------------------------------------------------------
__device__ __forceinline__ unsigned f2tf32(float f) {
    unsigned u;
    asm("cvt.rna.tf32.f32 %0, %1;" : "=r"(u) : "f"(f));
    return u;
}
__device__ __forceinline__ void split_tf32(float v, unsigned& hi, unsigned& lo) {
    hi = f2tf32(v);
    lo = f2tf32(v - __uint_as_float(hi));
}
__device__ __forceinline__ unsigned pack_bf16x2(float lo, float hi) {
    unsigned r;
    asm("cvt.rn.bf16x2.f32 %0, %1, %2;" : "=r"(r) : "f"(hi), "f"(lo));
    return r;
}

__device__ __forceinline__ void mma16n8k8(float* c, const unsigned* a, const unsigned* b) {
    asm volatile(
        "mma.sync.aligned.m16n8k8.row.col.f32.tf32.tf32.f32 "
        "{%0,%1,%2,%3}, {%4,%5,%6,%7}, {%8,%9}, {%0,%1,%2,%3};\n"
        : "+f"(c[0]), "+f"(c[1]), "+f"(c[2]), "+f"(c[3])
        : "r"(a[0]), "r"(a[1]), "r"(a[2]), "r"(a[3]), "r"(b[0]), "r"(b[1]));
}
__device__ __forceinline__ void mma16n8k16bf(float* c, const unsigned* a, const unsigned* b) {
    asm volatile(
        "mma.sync.aligned.m16n8k16.row.col.f32.bf16.bf16.f32 "
        "{%0,%1,%2,%3}, {%4,%5,%6,%7}, {%8,%9}, {%0,%1,%2,%3};\n"
        : "+f"(c[0]), "+f"(c[1]), "+f"(c[2]), "+f"(c[3])
        : "r"(a[0]), "r"(a[1]), "r"(a[2]), "r"(a[3]), "r"(b[0]), "r"(b[1]));
}

#define CP_ASYNC16(smem_u32, gptr) \
    asm volatile("cp.async.cg.shared.global [%0], [%1], 16;\n" :: "r"(smem_u32), "l"(gptr))
#define CP_COMMIT() asm volatile("cp.async.commit_group;\n" ::: "memory")
#define CP_WAIT0()  asm volatile("cp.async.wait_group 0;\n" ::: "memory")

// XOR swizzle for transposed fp32 [k][128] tiles
#define SWZ(k, col) ((col) ^ (((k) & 3) << 3))

__device__ __forceinline__ const float* w_row_ptr(int o, const float* Wq,
                                                  const float* Wk, const float* Wv) {
    if (o < C8)      return Wq + (size_t)o * NF;
    if (o < 2 * C8)  return Wk + (size_t)(o - C8) * NF;
    return Wv + (size_t)(o - 2 * C8) * NF;
}
__device__ __forceinline__ float bias_val(int o, const float* bq,
                                          const float* bk, const float* bv) {
    if (o < C8)      return bq[o];
    if (o < 2 * C8)  return bk[o - C8];
    return bv[o - 2 * C8];
}

// ---------------------------------------------------------------------------
// Kernel 1: QKV projection. C[o,n] = sum_c W[o,c]*x[b,c,n] + bias[o]
// HP (q/k rows, m 0..127): 3xTF32, fp32 out to g_qk.
// LP (v rows, m 128..639): 1xTF32, bf16 out to g_vbf.
// ---------------------------------------------------------------------------
template<bool HP>
__global__ __launch_bounds__(256) void qkv_mma(
    const float* __restrict__ x,
    const float* __restrict__ Wq, const float* __restrict__ bq,
    const float* __restrict__ Wk, const float* __restrict__ bk,
    const float* __restrict__ Wv, const float* __restrict__ bv,
    int m_base)
{
    __shared__ float As[2][128][20];
    __shared__ float Bs[2][16][128];

    const int b     = blockIdx.z;
    const int m_blk = m_base + blockIdx.y * 128;
    const int n_blk = blockIdx.x * 128;
    const float* xb = x + (size_t)b * NF * HW;

    const int tid  = threadIdx.x;
    const int warp = tid >> 5, lane = tid & 31;
    const int g    = lane >> 2, tig = lane & 3;
    const int wm   = (warp >> 2) * 64, wn = (warp & 3) * 32;

    const unsigned as0 = (unsigned)__cvta_generic_to_shared(&As[0][0][0]);
    const unsigned bs0 = (unsigned)__cvta_generic_to_shared(&Bs[0][0][0]);

    float acc[4][4][4] = {};
    const int T = NF / 16;   // 32

    {
        const int k0 = 0;
        int c = tid, row = c >> 2, off = (c & 3) * 4;
        CP_ASYNC16(as0 + row * 80 + off * 4, w_row_ptr(m_blk + row, Wq, Wk, Wv) + k0 + off);
        c = tid + 256; row = c >> 2; off = (c & 3) * 4;
        CP_ASYNC16(as0 + row * 80 + off * 4, w_row_ptr(m_blk + row, Wq, Wk, Wv) + k0 + off);
        c = tid;       { int r = c >> 5, o2 = (c & 31) * 4, sw = SWZ(r, o2);
            CP_ASYNC16(bs0 + r * 512 + sw * 4, xb + (size_t)(k0 + r) * HW + n_blk + o2); }
        c = tid + 256; { int r = c >> 5, o2 = (c & 31) * 4, sw = SWZ(r, o2);
            CP_ASYNC16(bs0 + r * 512 + sw * 4, xb + (size_t)(k0 + r) * HW + n_blk + o2); }
        CP_COMMIT();
    }

    for (int t = 0; t < T; ++t) {
        CP_WAIT0();
        __syncthreads();
        if (t + 1 < T) {
            const int s = (t + 1) & 1;
            const int k0 = (t + 1) * 16;
            int c = tid, row = c >> 2, off = (c & 3) * 4;
            CP_ASYNC16(as0 + s * 10240 + row * 80 + off * 4,
                       w_row_ptr(m_blk + row, Wq, Wk, Wv) + k0 + off);
            c = tid + 256; row = c >> 2; off = (c & 3) * 4;
            CP_ASYNC16(as0 + s * 10240 + row * 80 + off * 4,
                       w_row_ptr(m_blk + row, Wq, Wk, Wv) + k0 + off);
            c = tid;       { int r = c >> 5, o2 = (c & 31) * 4, sw = SWZ(r, o2);
                CP_ASYNC16(bs0 + s * 8192 + r * 512 + sw * 4,
                           xb + (size_t)(k0 + r) * HW + n_blk + o2); }
            c = tid + 256; { int r = c >> 5, o2 = (c & 31) * 4, sw = SWZ(r, o2);
                CP_ASYNC16(bs0 + s * 8192 + r * 512 + sw * 4,
                           xb + (size_t)(k0 + r) * HW + n_blk + o2); }
            CP_COMMIT();
        }
        const int s = t & 1;
        #pragma unroll
        for (int ks = 0; ks < 16; ks += 8) {
            unsigned af[4][4], bf[4][2];
            unsigned afl[4][4], bfl[4][2];
            #pragma unroll
            for (int mi = 0; mi < 4; ++mi) {
                const int row = wm + mi * 16 + g;
                float a0 = As[s][row][ks + tig];
                float a1 = As[s][row + 8][ks + tig];
                float a2 = As[s][row][ks + tig + 4];
                float a3 = As[s][row + 8][ks + tig + 4];
                if (HP) {
                    split_tf32(a0, af[mi][0], afl[mi][0]);
                    split_tf32(a1, af[mi][1], afl[mi][1]);
                    split_tf32(a2, af[mi][2], afl[mi][2]);
                    split_tf32(a3, af[mi][3], afl[mi][3]);
                } else {
                    af[mi][0] = f2tf32(a0); af[mi][1] = f2tf32(a1);
                    af[mi][2] = f2tf32(a2); af[mi][3] = f2tf32(a3);
                }
            }
            #pragma unroll
            for (int ni = 0; ni < 4; ++ni) {
                const int n = wn + ni * 8 + g;
                const int k0q = ks + tig, k1q = ks + tig + 4;
                float b0 = Bs[s][k0q][SWZ(k0q, n)];
                float b1 = Bs[s][k1q][SWZ(k1q, n)];
                if (HP) {
                    split_tf32(b0, bf[ni][0], bfl[ni][0]);
                    split_tf32(b1, bf[ni][1], bfl[ni][1]);
                } else {
                    bf[ni][0] = f2tf32(b0); bf[ni][1] = f2tf32(b1);
                }
            }
            #pragma unroll
            for (int mi = 0; mi < 4; ++mi)
                #pragma unroll
                for (int ni = 0; ni < 4; ++ni) {
                    mma16n8k8(acc[mi][ni], af[mi], bf[ni]);
                    if (HP) {
                        mma16n8k8(acc[mi][ni], afl[mi], bf[ni]);
                        mma16n8k8(acc[mi][ni], af[mi], bfl[ni]);
                    }
                }
        }
    }

    #pragma unroll
    for (int mi = 0; mi < 4; ++mi) {
        #pragma unroll
        for (int ni = 0; ni < 4; ++ni) {
            const int m = m_blk + wm + mi * 16 + g;
            const int n = n_blk + wn + ni * 8 + tig * 2;
            const float bias0 = bias_val(m, bq, bk, bv);
            const float bias1 = bias_val(m + 8, bq, bk, bv);
            float v00 = acc[mi][ni][0] + bias0, v01 = acc[mi][ni][1] + bias0;
            float v10 = acc[mi][ni][2] + bias1, v11 = acc[mi][ni][3] + bias1;
            if (HP) {
                float* outp = g_qk + (size_t)b * 2 * C8 * HW;
                *(float2*)(outp + (size_t)m * HW + n)       = make_float2(v00, v01);
                *(float2*)(outp + (size_t)(m + 8) * HW + n) = make_float2(v10, v11);
            } else {
                __nv_bfloat16* outp = g_vbf + (size_t)b * NF * HW;
                const int vm = m - 2 * C8;
                *(unsigned*)(outp + (size_t)vm * HW + n)       = pack_bf16x2(v00, v01);
                *(unsigned*)(outp + (size_t)(vm + 8) * HW + n) = pack_bf16x2(v10, v11);
            }
        }
    }
}

// ---------------------------------------------------------------------------
// Kernel 2: scores[i,j] = sum_c k[c,i]*q[c,j]  (3xTF32, K=64) -> fp32
// ---------------------------------------------------------------------------
__global__ __launch_bounds__(256) void scores_mma()
{
    __shared__ float Ks[2][16][128];
    __shared__ float Qs[2][16][128];

    const int b     = blockIdx.z;
    const int m_blk = blockIdx.y * 128;   // i
    const int n_blk = blockIdx.x * 128;   // j
    const float* qp = g_qk + (size_t)b * 2 * C8 * HW;
    const float* kp = qp + (size_t)C8 * HW;
    float* cp = g_attn + (size_t)b * HW * HW;

    const int tid  = threadIdx.x;
    const int warp = tid >> 5, lane = tid & 31;
    const int g    = lane >> 2, tig = lane & 3;
    const int wm   = (warp >> 2) * 64, wn = (warp & 3) * 32;

    const unsigned ks0 = (unsigned)__cvta_generic_to_shared(&Ks[0][0][0]);
    const unsigned qs0 = (unsigned)__cvta_generic_to_shared(&Qs[0][0][0]);

    float acc[4][4][4] = {};
    const int T = C8 / 16;   // 4

    {
        const int k0 = 0;
        #pragma unroll
        for (int h = 0; h < 2; ++h) {
            const int c = tid + h * 256;
            const int r = c >> 5, o2 = (c & 31) * 4, sw = SWZ(r, o2);
            CP_ASYNC16(ks0 + r * 512 + sw * 4, kp + (size_t)(k0 + r) * HW + m_blk + o2);
            CP_ASYNC16(qs0 + r * 512 + sw * 4, qp + (size_t)(k0 + r) * HW + n_blk + o2);
        }
        CP_COMMIT();
    }

    for (int t = 0; t < T; ++t) {
        CP_WAIT0();
        __syncthreads();
        if (t + 1 < T) {
            const int s = (t + 1) & 1;
            const int k0 = (t + 1) * 16;
            #pragma unroll
            for (int h = 0; h < 2; ++h) {
                const int c = tid + h * 256;
                const int r = c >> 5, o2 = (c & 31) * 4, sw = SWZ(r, o2);
                CP_ASYNC16(ks0 + s * 8192 + r * 512 + sw * 4,
                           kp + (size_t)(k0 + r) * HW + m_blk + o2);
                CP_ASYNC16(qs0 + s * 8192 + r * 512 + sw * 4,
                           qp + (size_t)(k0 + r) * HW + n_blk + o2);
            }
            CP_COMMIT();
        }
        const int s = t & 1;
        #pragma unroll
        for (int ks = 0; ks < 16; ks += 8) {
            const int ka = ks + tig, kb = ks + tig + 4;
            unsigned af[4][4], afl[4][4], bf[4][2], bfl[4][2];
            #pragma unroll
            for (int mi = 0; mi < 4; ++mi) {
                const int m = wm + mi * 16 + g;
                split_tf32(Ks[s][ka][SWZ(ka, m)],     af[mi][0], afl[mi][0]);
                split_tf32(Ks[s][ka][SWZ(ka, m + 8)], af[mi][1], afl[mi][1]);
                split_tf32(Ks[s][kb][SWZ(kb, m)],     af[mi][2], afl[mi][2]);
                split_tf32(Ks[s][kb][SWZ(kb, m + 8)], af[mi][3], afl[mi][3]);
            }
            #pragma unroll
            for (int ni = 0; ni < 4; ++ni) {
                const int n = wn + ni * 8 + g;
                split_tf32(Qs[s][ka][SWZ(ka, n)], bf[ni][0], bfl[ni][0]);
                split_tf32(Qs[s][kb][SWZ(kb, n)], bf[ni][1], bfl[ni][1]);
            }
            #pragma unroll
            for (int mi = 0; mi < 4; ++mi)
                #pragma unroll
                for (int ni = 0; ni < 4; ++ni) {
                    mma16n8k8(acc[mi][ni], af[mi], bf[ni]);
                    mma16n8k8(acc[mi][ni], afl[mi], bf[ni]);
                    mma16n8k8(acc[mi][ni], af[mi], bfl[ni]);
                }
        }
    }

    #pragma unroll
    for (int mi = 0; mi < 4; ++mi) {
        #pragma unroll
        for (int ni = 0; ni < 4; ++ni) {
            const int m = m_blk + wm + mi * 16 + g;
            const int n = n_blk + wn + ni * 8 + tig * 2;
            *(float2*)(cp + (size_t)m * HW + n)       = make_float2(acc[mi][ni][0], acc[mi][ni][1]);
            *(float2*)(cp + (size_t)(m + 8) * HW + n) = make_float2(acc[mi][ni][2], acc[mi][ni][3]);
        }
    }
}

// ---------------------------------------------------------------------------
// Kernel 3: row softmax (fp32 in -> bf16 out). One block per row.
// ---------------------------------------------------------------------------
__device__ __forceinline__ float warp_max(float v) {
    #pragma unroll
    for (int o = 16; o > 0; o >>= 1) v = fmaxf(v, __shfl_xor_sync(0xffffffffu, v, o));
    return v;
}
__device__ __forceinline__ float warp_sum(float v) {
    #pragma unroll
    for (int o = 16; o > 0; o >>= 1) v += __shfl_xor_sync(0xffffffffu, v, o);
    return v;
}

__global__ __launch_bounds__(256) void softmax_kernel()
{
    const float* p  = g_attn + (size_t)blockIdx.x * HW;
    __nv_bfloat16* pb = g_attn_bf + (size_t)blockIdx.x * HW;
    const int tid = threadIdx.x;

    float4 v[4];
    #pragma unroll
    for (int i = 0; i < 4; ++i)
        v[i] = ((const float4*)p)[tid + 256 * i];

    float m = -3.4e38f;
    #pragma unroll
    for (int i = 0; i < 4; ++i)
        m = fmaxf(m, fmaxf(fmaxf(v[i].x, v[i].y), fmaxf(v[i].z, v[i].w)));

    __shared__ float red[8];
    float wm = warp_max(m);
    if ((tid & 31) == 0) red[tid >> 5] = wm;
    __syncthreads();
    float bm = red[0];
    #pragma unroll
    for (int i = 1; i < 8; ++i) bm = fmaxf(bm, red[i]);

    float s = 0.0f;
    #pragma unroll
    for (int i = 0; i < 4; ++i) {
        v[i].x = __expf(v[i].x - bm);
        v[i].y = __expf(v[i].y - bm);
        v[i].z = __expf(v[i].z - bm);
        v[i].w = __expf(v[i].w - bm);
        s += v[i].x + v[i].y + v[i].z + v[i].w;
    }
    __syncthreads();
    float ws = warp_sum(s);
    if ((tid & 31) == 0) red[tid >> 5] = ws;
    __syncthreads();
    float total = 0.0f;
    #pragma unroll
    for (int i = 0; i < 8; ++i) total += red[i];
    const float inv = 1.0f / total;

    #pragma unroll
    for (int i = 0; i < 4; ++i) {
        uint2 o;
        o.x = pack_bf16x2(v[i].x * inv, v[i].y * inv);
        o.y = pack_bf16x2(v[i].z * inv, v[i].w * inv);
        ((uint2*)pb)[tid + 256 * i] = o;
    }
}

// ---------------------------------------------------------------------------
// Kernel 4: out[c,i] = x[c,i] + alpha * sum_j v[c,j]*attn[i,j]
// bf16 mma m16n8k16. A = v bf16 [m][k], B = attn bf16 [n][k].
// Smem: [128][40] bf16 (pad 32->40) -> conflict-free 32b fragment loads.
// ---------------------------------------------------------------------------
__global__ __launch_bounds__(256, 2) void out_mma_bf(
    const float* __restrict__ x,
    const float* __restrict__ alphap,
    float* __restrict__ out)
{
    __shared__ __nv_bfloat16 As[2][128][40];
    __shared__ __nv_bfloat16 Bs[2][128][40];

    const int b     = blockIdx.z;
    const int m_blk = blockIdx.y * 128;   // c
    const int n_blk = blockIdx.x * 128;   // i
    const __nv_bfloat16* vp = g_vbf + (size_t)b * NF * HW;
    const __nv_bfloat16* ap = g_attn_bf + (size_t)b * HW * HW;
    const float* xb = x + (size_t)b * NF * HW;
    float* ob = out + (size_t)b * NF * HW;

    const int tid  = threadIdx.x;
    const int warp = tid >> 5, lane = tid & 31;
    const int g    = lane >> 2, tig = lane & 3;
    const int wm   = (warp >> 2) * 64, wn = (warp & 3) * 32;

    const unsigned as0 = (unsigned)__cvta_generic_to_shared(&As[0][0][0]);
    const unsigned bs0 = (unsigned)__cvta_generic_to_shared(&Bs[0][0][0]);

    float acc[4][4][4] = {};
    const int T = HW / 32;   // 128 stages of kt=32

    // per stage: each array needs 128 rows x 64B = 512 chunks of 16B
    {
        const int k0 = 0;
        #pragma unroll
        for (int h = 0; h < 2; ++h) {
            const int c = tid + h * 256;
            const int row = c >> 2;            // 4 chunks per row
            const int offb = (c & 3) * 16;     // byte offset in row
            const int offe = (c & 3) * 8;      // element offset
            CP_ASYNC16(as0 + row * 80 + offb, vp + (size_t)(m_blk + row) * HW + k0 + offe);
            CP_ASYNC16(bs0 + row * 80 + offb, ap + (size_t)(n_blk + row) * HW + k0 + offe);
        }
        CP_COMMIT();
    }

    for (int t = 0; t < T; ++t) {
        CP_WAIT0();
        __syncthreads();
        if (t + 1 < T) {
            const int s = (t + 1) & 1;
            const int k0 = (t + 1) * 32;
            #pragma unroll
            for (int h = 0; h < 2; ++h) {
                const int c = tid + h * 256;
                const int row = c >> 2;
                const int offb = (c & 3) * 16;
                const int offe = (c & 3) * 8;
                CP_ASYNC16(as0 + s * 10240 + row * 80 + offb,
                           vp + (size_t)(m_blk + row) * HW + k0 + offe);
                CP_ASYNC16(bs0 + s * 10240 + row * 80 + offb,
                           ap + (size_t)(n_blk + row) * HW + k0 + offe);
            }
            CP_COMMIT();
        }
        const int s = t & 1;
        #pragma unroll
        for (int ks = 0; ks < 32; ks += 16) {
            unsigned af[4][4], bf[4][2];
            #pragma unroll
            for (int mi = 0; mi < 4; ++mi) {
                const int row = wm + mi * 16 + g;
                af[mi][0] = *(const unsigned*)&As[s][row][ks + 2 * tig];
                af[mi][1] = *(const unsigned*)&As[s][row + 8][ks + 2 * tig];
                af[mi][2] = *(const unsigned*)&As[s][row][ks + 8 + 2 * tig];
                af[mi][3] = *(const unsigned*)&As[s][row + 8][ks + 8 + 2 * tig];
            }
            #pragma unroll
            for (int ni = 0; ni < 4; ++ni) {
                const int n = wn + ni * 8 + g;
                bf[ni][0] = *(const unsigned*)&Bs[s][n][ks + 2 * tig];
                bf[ni][1] = *(const unsigned*)&Bs[s][n][ks + 8 + 2 * tig];
            }
            #pragma unroll
            for (int mi = 0; mi < 4; ++mi)
                #pragma unroll
                for (int ni = 0; ni < 4; ++ni)
                    mma16n8k16bf(acc[mi][ni], af[mi], bf[ni]);
        }
    }

    const float alpha = alphap[0];
    #pragma unroll
    for (int mi = 0; mi < 4; ++mi) {
        #pragma unroll
        for (int ni = 0; ni < 4; ++ni) {
            const int m = m_blk + wm + mi * 16 + g;
            const int n = n_blk + wn + ni * 8 + tig * 2;
            const size_t i0 = (size_t)m * HW + n;
            const size_t i1 = (size_t)(m + 8) * HW + n;
            float2 x0 = *(const float2*)(xb + i0);
            float2 x1 = *(const float2*)(xb + i1);
            float2 r0 = { x0.x + alpha * acc[mi][ni][0], x0.y + alpha * acc[mi][ni][1] };
            float2 r1 = { x1.x + alpha * acc[mi][ni][2], x1.y + alpha * acc[mi][ni][3] };
            *(float2*)(ob + i0) = r0;
            *(float2*)(ob + i1) = r1;
        }
    }
}

// ---------------------------------------------------------------------------
extern "C" void kernel_launch(void* const* d_in, const int* in_sizes, int n_in,
                              void* d_out, int out_size)
{
    const float* x     = (const float*)d_in[0];
    const float* Wq    = (const float*)d_in[1];
    const float* bq    = (const float*)d_in[2];
    const float* Wk    = (const float*)d_in[3];
    const float* bk    = (const float*)d_in[4];
    const float* Wv    = (const float*)d_in[5];
    const float* bv    = (const float*)d_in[6];
    const float* alpha = (const float*)d_in[7];
    float* out = (float*)d_out;

    // q/k rows (0..127): 3xTF32, fp32 out
    qkv_mma<true><<<dim3(HW / 128, 1, BSZ), 256>>>(x, Wq, bq, Wk, bk, Wv, bv, 0);
    // v rows (128..639): 1xTF32, bf16 out
    qkv_mma<false><<<dim3(HW / 128, 4, BSZ), 256>>>(x, Wq, bq, Wk, bk, Wv, bv, 128);
    scores_mma<<<dim3(HW / 128, HW / 128, BSZ), 256>>>();
    softmax_kernel<<<BSZ * HW, 256>>>();
    out_mma_bf<<<dim3(HW / 128, NF / 128, BSZ), 256>>>(x, alpha, out);
}